// round 6
// baseline (speedup 1.0000x reference)
#include <cuda_runtime.h>
#include <cstdint>

// Problem constants (fixed by the reference).
#define ROWS       8192
#define COLS       8192
#define NUMEL      (1ULL * ROWS * COLS)          // 64M output floats
#define NCODES     (NUMEL / 4)                   // 16M codes (centroid_len = 4)
#define CB_ENTRIES 512                           // 2 codebooks * 256 centroids (float4 each)

#define BLOCK      256
#define BLOCKS_PER_SM 8
#define CODES_PER_THREAD 8
#define TILE_CODES (BLOCK * CODES_PER_THREAD)    // 2048
#define NTILES     ((int)(NCODES / TILE_CODES))  // 8192 (exact)
#define GRID       (152 * BLOCKS_PER_SM)         // 1216

// Codebook staged to smem once per block. Each block owns a CONTIGUOUS,
// balanced range of tiles (sequential DRAM sweep, good row locality).
// Interleaved per-thread layout inside a tile keeps every LDG/STG coalesced.
// Streaming cache hints: codes/output are touched exactly once.
__global__ __launch_bounds__(BLOCK, BLOCKS_PER_SM) void dequant_kernel(
    const float4* __restrict__ codebooks,   // [512] float4
    const float*  __restrict__ scales,      // [NUMEL/64]
    const int*    __restrict__ codes,       // [NCODES]
    float4*       __restrict__ out4)        // [NCODES]
{
    __shared__ float4 s_cb[CB_ENTRIES];
    for (int i = threadIdx.x; i < CB_ENTRIES; i += BLOCK)
        s_cb[i] = codebooks[i];
    __syncthreads();

    const int t = threadIdx.x;

    // Balanced contiguous partition: first `rem` blocks get (base+1) tiles.
    const int base_cnt = NTILES / GRID;              // 6
    const int rem      = NTILES % GRID;              // 896
    const int cnt   = base_cnt + (blockIdx.x < rem ? 1 : 0);
    const int first = blockIdx.x * base_cnt + min((int)blockIdx.x, rem);

    for (int tile = first; tile < first + cnt; tile++) {
        const long long base = (long long)tile * TILE_CODES;
        // Codebook half: first 8M codes -> cb 0, rest -> cb 1.
        // 8M / 2048 = 4096 tiles fall entirely in the first half.
        const int cb_off = (tile >= (NTILES / 2)) ? 256 : 0;

        const int*   cp = codes  + base;
        const float* sp = scales + (base >> 4);   // one scale per 16 codes
        float4*      op = out4   + base;

        int   c[CODES_PER_THREAD];
        float s[CODES_PER_THREAD];

        // Front-batch all global loads (MLP ~16, each instruction coalesced).
        #pragma unroll
        for (int k = 0; k < CODES_PER_THREAD; k++)
            c[k] = __ldcs(cp + k * BLOCK + t);          // streaming: no reuse
        #pragma unroll
        for (int k = 0; k < CODES_PER_THREAD; k++)
            s[k] = __ldg(sp + ((k * BLOCK + t) >> 4));  // shared within block -> cache

        // Gather from smem codebook, scale, store (coalesced STG.128, streaming).
        #pragma unroll
        for (int k = 0; k < CODES_PER_THREAD; k++) {
            float4 v = s_cb[cb_off + c[k]];
            v.x *= s[k]; v.y *= s[k]; v.z *= s[k]; v.w *= s[k];
            __stcs(op + k * BLOCK + t, v);
        }
    }
}

extern "C" void kernel_launch(void* const* d_in, const int* in_sizes, int n_in,
                              void* d_out, int out_size)
{
    // metadata order: codebooks [2,256,4] f32, scales [1M,1] f32, codes [2,8M] i32, rows, columns
    const float4* codebooks = (const float4*)d_in[0];
    const float*  scales    = (const float*)d_in[1];
    const int*    codes     = (const int*)d_in[2];
    float4*       out4      = (float4*)d_out;

    dequant_kernel<<<GRID, BLOCK>>>(codebooks, scales, codes, out4);
}

// round 7
// speedup vs baseline: 1.0496x; 1.0496x over previous
#include <cuda_runtime.h>
#include <cstdint>

// Problem constants (fixed by the reference).
#define ROWS       8192
#define COLS       8192
#define NUMEL      (1ULL * ROWS * COLS)          // 64M output floats
#define NCODES     (NUMEL / 4)                   // 16M codes (centroid_len = 4)
#define CB_ENTRIES 512                           // 2 codebooks * 256 centroids (float4 each)

#define BLOCK      256
#define CPT        8                              // codes per thread per tile
#define TILE_CODES (BLOCK * CPT)                  // 2048
#define NTILES     ((int)(NCODES / TILE_CODES))   // 8192 (exact)
#define GRID       (152 * 6)                      // 912 blocks (~6/SM at ~44 regs)

// Software-pipelined dequant: codebook in smem, grid-stride over tiles with
// code/scale loads prefetched one iteration ahead into explicit double
// buffers (A/B, loop unrolled x2 so all buffer indices are compile-time).
// Interleaved per-thread layout keeps every LDG/STG fully coalesced.

__device__ __forceinline__ void load_tile(
    const int* __restrict__ codes, const float* __restrict__ scales,
    int tile, int t, int* c, float* s)
{
    const long long base = (long long)tile * TILE_CODES;
    const int*   cp = codes  + base;
    const float* sp = scales + (base >> 4);
    #pragma unroll
    for (int k = 0; k < CPT; k++)
        c[k] = __ldg(cp + k * BLOCK + t);
    #pragma unroll
    for (int k = 0; k < CPT; k++)
        s[k] = __ldg(sp + ((k * BLOCK + t) >> 4));
}

__device__ __forceinline__ void process_tile(
    const float4* __restrict__ s_cb, float4* __restrict__ out4,
    int tile, int t, const int* c, const float* s)
{
    const long long base = (long long)tile * TILE_CODES;
    // First 4096 tiles lie entirely in codebook 0, rest in codebook 1.
    const int cb_off = (tile >= (NTILES / 2)) ? 256 : 0;
    float4* op = out4 + base;
    #pragma unroll
    for (int k = 0; k < CPT; k++) {
        float4 v = s_cb[cb_off + c[k]];
        v.x *= s[k]; v.y *= s[k]; v.z *= s[k]; v.w *= s[k];
        op[k * BLOCK + t] = v;
    }
}

__global__ __launch_bounds__(BLOCK) void dequant_kernel(
    const float4* __restrict__ codebooks,   // [512] float4
    const float*  __restrict__ scales,      // [NUMEL/64]
    const int*    __restrict__ codes,       // [NCODES]
    float4*       __restrict__ out4)        // [NCODES]
{
    __shared__ float4 s_cb[CB_ENTRIES];
    for (int i = threadIdx.x; i < CB_ENTRIES; i += BLOCK)
        s_cb[i] = codebooks[i];
    __syncthreads();

    const int t      = threadIdx.x;
    const int stride = gridDim.x;

    int tile = blockIdx.x;
    if (tile >= NTILES) return;

    int   cA[CPT], cB[CPT];
    float sA[CPT], sB[CPT];

    // Prologue: fill buffer A.
    load_tile(codes, scales, tile, t, cA, sA);

    while (true) {
        // --- consume A, prefetch into B ---
        {
            int nxt = tile + stride;
            if (nxt < NTILES)
                load_tile(codes, scales, nxt, t, cB, sB);
            process_tile(s_cb, out4, tile, t, cA, sA);
            tile = nxt;
            if (tile >= NTILES) break;
        }
        // --- consume B, prefetch into A ---
        {
            int nxt = tile + stride;
            if (nxt < NTILES)
                load_tile(codes, scales, nxt, t, cA, sA);
            process_tile(s_cb, out4, tile, t, cB, sB);
            tile = nxt;
            if (tile >= NTILES) break;
        }
    }
}

extern "C" void kernel_launch(void* const* d_in, const int* in_sizes, int n_in,
                              void* d_out, int out_size)
{
    // metadata order: codebooks [2,256,4] f32, scales [1M,1] f32, codes [2,8M] i32, rows, columns
    const float4* codebooks = (const float4*)d_in[0];
    const float*  scales    = (const float*)d_in[1];
    const int*    codes     = (const int*)d_in[2];
    float4*       out4      = (float4*)d_out;

    int grid = GRID;
    if (grid > NTILES) grid = NTILES;

    dequant_kernel<<<grid, BLOCK>>>(codebooks, scales, codes, out4);
}

// round 8
// speedup vs baseline: 1.0878x; 1.0364x over previous
#include <cuda_runtime.h>
#include <cstdint>

// Problem constants (fixed by the reference).
#define ROWS       8192
#define COLS       8192
#define NUMEL      (1ULL * ROWS * COLS)          // 64M output floats
#define NCODES     (NUMEL / 4)                   // 16M codes (centroid_len = 4)
#define CB_ENTRIES 512                           // 2 codebooks * 256 centroids (float4 each)

#define BLOCK      256
#define CPT        4                               // codes per thread per tile
#define TILE_CODES (BLOCK * CPT)                   // 1024 codes
#define TILE_BYTES (TILE_CODES * 16)               // 16 KB output per tile
#define NTILES     ((int)(NCODES / TILE_CODES))    // 16384 (exact)
#define GRID       (152 * 5)                       // 760 blocks (smem-limited 5/SM)

// Dequant with TMA bulk stores: compute a 16KB output tile into smem
// (double buffered), then one cp.async.bulk per tile streams it to GMEM as
// a single contiguous burst. Stores become fully async; DRAM sees large
// sequential write bursts instead of interleaved 128B STG wavefronts.

__global__ __launch_bounds__(BLOCK) void dequant_kernel(
    const float4* __restrict__ codebooks,   // [512] float4
    const float*  __restrict__ scales,      // [NUMEL/64]
    const int*    __restrict__ codes,       // [NCODES]
    float4*       __restrict__ out4)        // [NCODES]
{
    __shared__ float4 s_cb[CB_ENTRIES];                    // 8 KB
    __shared__ __align__(128) float4 s_out[2][TILE_CODES]; // 2 x 16 KB

    for (int i = threadIdx.x; i < CB_ENTRIES; i += BLOCK)
        s_cb[i] = codebooks[i];
    __syncthreads();

    const int t      = threadIdx.x;
    const int stride = gridDim.x;

    int iter = 0;
    for (int tile = blockIdx.x; tile < NTILES; tile += stride, iter++) {
        const int buf = iter & 1;
        const long long base = (long long)tile * TILE_CODES;
        // First 8192 tiles lie entirely in codebook 0, rest in codebook 1.
        const int cb_off = (tile >= (NTILES / 2)) ? 256 : 0;

        const int*   cp = codes  + base;
        const float* sp = scales + (base >> 4);

        // Front-batch global loads (in flight across the barrier below).
        int   c[CPT];
        float s[CPT];
        #pragma unroll
        for (int k = 0; k < CPT; k++)
            c[k] = __ldg(cp + k * BLOCK + t);
        #pragma unroll
        for (int k = 0; k < CPT; k++)
            s[k] = __ldg(sp + ((k * BLOCK + t) >> 4));

        // Make sure the TMA store issued 2 iterations ago (same buffer) has
        // finished READING this smem buffer before we overwrite it.
        if (iter >= 2 && t == 0)
            asm volatile("cp.async.bulk.wait_group.read 1;" ::: "memory");
        __syncthreads();

        // Gather + scale -> smem tile (interleaved STS.128, conflict-free).
        #pragma unroll
        for (int k = 0; k < CPT; k++) {
            float4 v = s_cb[cb_off + c[k]];
            v.x *= s[k]; v.y *= s[k]; v.z *= s[k]; v.w *= s[k];
            s_out[buf][k * BLOCK + t] = v;
        }
        __syncthreads();

        // One thread issues the bulk async store of the whole 16KB tile.
        if (t == 0) {
            asm volatile("fence.proxy.async.shared::cta;" ::: "memory");
            uint32_t src;
            asm("{ .reg .u64 a; cvta.to.shared.u64 a, %1; cvt.u32.u64 %0, a; }"
                : "=r"(src) : "l"(&s_out[buf][0]));
            asm volatile(
                "cp.async.bulk.global.shared::cta.bulk_group [%0], [%1], %2;"
                :: "l"(out4 + base), "r"(src), "n"(TILE_BYTES) : "memory");
            asm volatile("cp.async.bulk.commit_group;" ::: "memory");
        }
    }

    // Drain all outstanding bulk stores before exit.
    if (t == 0)
        asm volatile("cp.async.bulk.wait_group 0;" ::: "memory");
}

extern "C" void kernel_launch(void* const* d_in, const int* in_sizes, int n_in,
                              void* d_out, int out_size)
{
    // metadata order: codebooks [2,256,4] f32, scales [1M,1] f32, codes [2,8M] i32, rows, columns
    const float4* codebooks = (const float4*)d_in[0];
    const float*  scales    = (const float*)d_in[1];
    const int*    codes     = (const int*)d_in[2];
    float4*       out4      = (float4*)d_out;

    int grid = GRID;
    if (grid > NTILES) grid = NTILES;

    dequant_kernel<<<grid, BLOCK>>>(codebooks, scales, codes, out4);
}